// round 2
// baseline (speedup 1.0000x reference)
#include <cuda_runtime.h>
#include <math.h>

// Batched log(M) for SPD 64x64 matrices with spectrum in [1, 8]:
// degree-14 Chebyshev approximation of log on [1,8], evaluated as a matrix
// polynomial in T = (M - 4.5 I)/3.5 via Paterson-Stockmeyer (6 matmuls).

constexpr int DEG = 14;
constexpr int S   = 64;        // smem row stride (floats)
constexpr int MSZ = 64 * S;    // floats per 64x64 buffer

struct Poly { float a[DEG + 1]; };

// C[i0..i0+3][j0..j0+3] = sum_k A[k][i0..i0+3] * B[k][j0..j0+3]
// Valid because A is symmetric: A[i][k] == A[k][i]. Both operands are read
// as contiguous float4 row segments -> LDS.128, conflict-free.
__device__ __forceinline__ void mm64sym(const float* __restrict__ A,
                                        const float* __restrict__ B,
                                        float* __restrict__ C,
                                        int i0, int j0) {
    float acc[4][4];
#pragma unroll
    for (int r = 0; r < 4; ++r)
#pragma unroll
        for (int c = 0; c < 4; ++c) acc[r][c] = 0.0f;

#pragma unroll 4
    for (int k = 0; k < 64; ++k) {
        const float4 av = *reinterpret_cast<const float4*>(A + k * S + i0);
        const float4 bv = *reinterpret_cast<const float4*>(B + k * S + j0);
        const float ar[4] = {av.x, av.y, av.z, av.w};
        const float br[4] = {bv.x, bv.y, bv.z, bv.w};
#pragma unroll
        for (int r = 0; r < 4; ++r)
#pragma unroll
            for (int c = 0; c < 4; ++c) acc[r][c] += ar[r] * br[c];
    }
#pragma unroll
    for (int r = 0; r < 4; ++r) {
        float4 v = make_float4(acc[r][0], acc[r][1], acc[r][2], acc[r][3]);
        *reinterpret_cast<float4*>(C + (i0 + r) * S + j0) = v;
    }
}

__global__ __launch_bounds__(256, 2)
void logm_poly_kernel(const float* __restrict__ gin,
                      float* __restrict__ gout,
                      Poly P) {
    extern __shared__ float sm[];
    float* T  = sm;
    float* T2 = sm + 1 * MSZ;
    float* T3 = sm + 2 * MSZ;
    float* T4 = sm + 3 * MSZ;
    float* AC = sm + 4 * MSZ;
    float* TP = sm + 5 * MSZ;

    const int tid = threadIdx.x;
    const int i0  = (tid >> 4) * 4;
    const int j0  = (tid & 15) * 4;
    const float* gm = gin  + (size_t)blockIdx.x * 4096;
    float*       go = gout + (size_t)blockIdx.x * 4096;

    const float inv_beta = 1.0f / 3.5f;
    const float alpha    = 4.5f;

    // T = (M - alpha*I) / beta     (lambda(T) in [-1, 1])
    for (int e = tid; e < 1024; e += 256) {
        float4 v = reinterpret_cast<const float4*>(gm)[e];
        const int row = e >> 4;
        const int c0  = (e & 15) * 4;
        if (row >= c0 && row < c0 + 4) {
            float* vv = &v.x;
            vv[row - c0] -= alpha;
        }
        v.x *= inv_beta; v.y *= inv_beta; v.z *= inv_beta; v.w *= inv_beta;
        *reinterpret_cast<float4*>(T + row * S + c0) = v;
    }
    __syncthreads();

    mm64sym(T,  T,  T2, i0, j0); __syncthreads();   // T2 = T*T
    mm64sym(T2, T,  T3, i0, j0); __syncthreads();   // T3 = T2*T
    mm64sym(T2, T2, T4, i0, j0);                    // T4 = T2*T2

    // AC = a12*I + a13*T + a14*T2   (no sync needed: reads only T, T2)
#pragma unroll
    for (int r = 0; r < 4; ++r)
#pragma unroll
        for (int c = 0; c < 4; ++c) {
            const int i = i0 + r, j = j0 + c, o = i * S + j;
            float v = P.a[13] * T[o] + P.a[14] * T2[o];
            if (i == j) v += P.a[12];
            AC[o] = v;
        }
    __syncthreads();

    mm64sym(AC, T4, TP, i0, j0); __syncthreads();   // TP = AC*T4
    // AC = TP + a8*I + a9*T + a10*T2 + a11*T3
#pragma unroll
    for (int r = 0; r < 4; ++r)
#pragma unroll
        for (int c = 0; c < 4; ++c) {
            const int i = i0 + r, j = j0 + c, o = i * S + j;
            float v = TP[o] + P.a[9] * T[o] + P.a[10] * T2[o] + P.a[11] * T3[o];
            if (i == j) v += P.a[8];
            AC[o] = v;
        }
    __syncthreads();

    mm64sym(AC, T4, TP, i0, j0); __syncthreads();
    // AC = TP + a4*I + a5*T + a6*T2 + a7*T3
#pragma unroll
    for (int r = 0; r < 4; ++r)
#pragma unroll
        for (int c = 0; c < 4; ++c) {
            const int i = i0 + r, j = j0 + c, o = i * S + j;
            float v = TP[o] + P.a[5] * T[o] + P.a[6] * T2[o] + P.a[7] * T3[o];
            if (i == j) v += P.a[4];
            AC[o] = v;
        }
    __syncthreads();

    mm64sym(AC, T4, TP, i0, j0); __syncthreads();
    // out = TP + a0*I + a1*T + a2*T2 + a3*T3  -> global
#pragma unroll
    for (int r = 0; r < 4; ++r) {
        float4 v;
        float* vp = &v.x;
#pragma unroll
        for (int c = 0; c < 4; ++c) {
            const int i = i0 + r, j = j0 + c, o = i * S + j;
            float x = TP[o] + P.a[1] * T[o] + P.a[2] * T2[o] + P.a[3] * T3[o];
            if (i == j) x += P.a[0];
            vp[c] = x;
        }
        *reinterpret_cast<float4*>(go + (i0 + r) * 64 + j0) = v;
    }
}

extern "C" void kernel_launch(void* const* d_in, const int* in_sizes, int n_in,
                              void* d_out, int out_size) {
    const float* in = (const float*)d_in[0];
    float* out = (float*)d_out;
    const int nmat = in_sizes[0] / 4096;   // 8192 matrices of 64x64

    // Chebyshev coefficients of log(x) on [a,b] = [1,8], closed form:
    //   x = alpha + beta*t, t = cos(theta)
    //   log(alpha + beta*cos th) = log A + 2*sum_k (-1)^{k+1} r^k cos(k th)/k
    //   with r = (alpha - sqrt(alpha^2-beta^2))/beta, A = alpha/(1+r^2).
    // Then convert Chebyshev -> monomial basis in t (coeffs stay O(1) since 2r<1).
    Poly P;
    {
        const double alpha = 4.5, beta = 3.5;
        const double r = (alpha - sqrt(alpha * alpha - beta * beta)) / beta;
        double c[DEG + 1];
        c[0] = log(alpha / (1.0 + r * r));
        double rk = 1.0;
        for (int k = 1; k <= DEG; ++k) {
            rk *= r;
            c[k] = ((k & 1) ? 2.0 : -2.0) * rk / (double)k;
        }
        double mono[DEG + 1], Tm1[DEG + 1], Tc[DEG + 1], Tn[DEG + 1];
        for (int j = 0; j <= DEG; ++j) { mono[j] = 0; Tm1[j] = 0; Tc[j] = 0; }
        Tm1[0] = 1.0;            // T0
        Tc[1]  = 1.0;            // T1
        for (int j = 0; j <= DEG; ++j) mono[j] = c[0] * Tm1[j] + c[1] * Tc[j];
        for (int k = 2; k <= DEG; ++k) {
            for (int j = 0; j <= DEG; ++j) {
                double t = -Tm1[j];
                if (j > 0) t += 2.0 * Tc[j - 1];
                Tn[j] = t;
            }
            for (int j = 0; j <= DEG; ++j) {
                mono[j] += c[k] * Tn[j];
                Tm1[j] = Tc[j];
                Tc[j]  = Tn[j];
            }
        }
        for (int j = 0; j <= DEG; ++j) P.a[j] = (float)mono[j];
    }

    const size_t smem_bytes = 6 * MSZ * sizeof(float);   // 96 KB
    cudaFuncSetAttribute(logm_poly_kernel,
                         cudaFuncAttributeMaxDynamicSharedMemorySize,
                         (int)smem_bytes);
    logm_poly_kernel<<<nmat, 256, smem_bytes>>>(in, out, P);
}

// round 3
// speedup vs baseline: 1.4205x; 1.4205x over previous
#include <cuda_runtime.h>
#include <math.h>
#include <stdint.h>

// Batched log(M) for SPD 64x64 matrices, spectrum in [1, 8]:
// degree-11 Chebyshev approx of log on [1,8] in T = (M - 4.5 I)/3.5,
// Paterson-Stockmeyer s=3 (5 matmuls), inner product via packed fma.rn.f32x2.

constexpr int DEG = 11;
constexpr int S   = 64;        // smem row stride (floats)
constexpr int MSZ = 64 * S;    // floats per 64x64 buffer

struct Poly { float a[DEG + 1]; };

typedef unsigned long long u64;

__device__ __forceinline__ u64 splat2(float x) {
    u64 r; asm("mov.b64 %0, {%1, %1};" : "=l"(r) : "f"(x)); return r;
}
__device__ __forceinline__ u64 pack2(float lo, float hi) {
    u64 r; asm("mov.b64 %0, {%1, %2};" : "=l"(r) : "f"(lo), "f"(hi)); return r;
}
__device__ __forceinline__ void fma2(u64& d, u64 a, u64 b) {
    asm("fma.rn.f32x2 %0, %1, %2, %0;" : "+l"(d) : "l"(a), "l"(b));
}
__device__ __forceinline__ void add2(u64& d, u64 a) {
    asm("add.rn.f32x2 %0, %0, %1;" : "+l"(d) : "l"(a));
}

// acc[r][cp] = packed pair (C[i0+r][j0+2cp], C[i0+r][j0+2cp+1]),
// C = A^T B = A B for symmetric A. Both operands stream as LDS.128 row reads.
__device__ __forceinline__ void mm64(const float* __restrict__ A,
                                     const float* __restrict__ B,
                                     int i0, int j0, u64 acc[4][2]) {
#pragma unroll
    for (int r = 0; r < 4; ++r) { acc[r][0] = 0ull; acc[r][1] = 0ull; }
    const float* ap = A + i0;
    const float* bp = B + j0;
#pragma unroll 16
    for (int k = 0; k < 64; ++k) {
        const float4     av = *reinterpret_cast<const float4*>(ap + k * S);
        const ulonglong2 bv = *reinterpret_cast<const ulonglong2*>(bp + k * S);
        const u64 a0 = splat2(av.x), a1 = splat2(av.y);
        const u64 a2 = splat2(av.z), a3 = splat2(av.w);
        fma2(acc[0][0], a0, bv.x); fma2(acc[0][1], a0, bv.y);
        fma2(acc[1][0], a1, bv.x); fma2(acc[1][1], a1, bv.y);
        fma2(acc[2][0], a2, bv.x); fma2(acc[2][1], a2, bv.y);
        fma2(acc[3][0], a3, bv.x); fma2(acc[3][1], a3, bv.y);
    }
}

// acc += c0*I + c1*T + c2*T2 on this thread's tile (register-resident).
__device__ __forceinline__ void addpoly(u64 acc[4][2],
                                        const float* __restrict__ T,
                                        const float* __restrict__ T2,
                                        float c0, float c1, float c2,
                                        int i0, int j0) {
    const u64 c1s = splat2(c1), c2s = splat2(c2);
#pragma unroll
    for (int r = 0; r < 4; ++r) {
        const ulonglong2 tv = *reinterpret_cast<const ulonglong2*>(T  + (i0 + r) * S + j0);
        const ulonglong2 sv = *reinterpret_cast<const ulonglong2*>(T2 + (i0 + r) * S + j0);
        fma2(acc[r][0], c1s, tv.x); fma2(acc[r][1], c1s, tv.y);
        fma2(acc[r][0], c2s, sv.x); fma2(acc[r][1], c2s, sv.y);
    }
    if (i0 == j0) {           // diagonal hits this tile iff i0 == j0
#pragma unroll
        for (int r = 0; r < 4; ++r) {
            const u64 d = (r & 1) ? pack2(0.0f, c0) : pack2(c0, 0.0f);
            add2(acc[r][r >> 1], d);
        }
    }
}

__device__ __forceinline__ void store_tile(float* __restrict__ C,
                                           int i0, int j0, const u64 acc[4][2]) {
#pragma unroll
    for (int r = 0; r < 4; ++r)
        *reinterpret_cast<ulonglong2*>(C + (i0 + r) * S + j0) =
            make_ulonglong2(acc[r][0], acc[r][1]);
}

__global__ __launch_bounds__(256, 3)
void logm_poly_kernel(const float* __restrict__ gin,
                      float* __restrict__ gout,
                      Poly P) {
    extern __shared__ float sm[];
    float* T  = sm;
    float* T2 = sm + 1 * MSZ;
    float* T3 = sm + 2 * MSZ;
    float* AC = sm + 3 * MSZ;

    const int tid = threadIdx.x;
    const int i0  = (tid >> 4) * 4;
    const int j0  = (tid & 15) * 4;
    const float* gm = gin  + (size_t)blockIdx.x * 4096;
    float*       go = gout + (size_t)blockIdx.x * 4096;

    const float inv_beta = 1.0f / 3.5f;
    const float alpha    = 4.5f;

    // T = (M - alpha*I) / beta     (lambda(T) in [-1, 1])
    for (int e = tid; e < 1024; e += 256) {
        float4 v = reinterpret_cast<const float4*>(gm)[e];
        const int row = e >> 4;
        const int c0  = (e & 15) * 4;
        if (row >= c0 && row < c0 + 4) {
            float* vv = &v.x;
            vv[row - c0] -= alpha;
        }
        v.x *= inv_beta; v.y *= inv_beta; v.z *= inv_beta; v.w *= inv_beta;
        *reinterpret_cast<float4*>(T + row * S + c0) = v;
    }
    __syncthreads();

    u64 acc[4][2];

    // T2 = T*T
    mm64(T, T, i0, j0, acc);
    store_tile(T2, i0, j0, acc);
    __syncthreads();

    // T3 = T2*T ; AC = a9*I + a10*T + a11*T2  (both only read T, T2)
    mm64(T2, T, i0, j0, acc);
    store_tile(T3, i0, j0, acc);
    {
        u64 c3[4][2];
#pragma unroll
        for (int r = 0; r < 4; ++r) { c3[r][0] = 0ull; c3[r][1] = 0ull; }
        addpoly(c3, T, T2, P.a[9], P.a[10], P.a[11], i0, j0);
        store_tile(AC, i0, j0, c3);
    }
    __syncthreads();

    // Horner step 1: AC = AC*T3 + a6*I + a7*T + a8*T2
    mm64(AC, T3, i0, j0, acc);
    addpoly(acc, T, T2, P.a[6], P.a[7], P.a[8], i0, j0);
    __syncthreads();                       // all reads of old AC done
    store_tile(AC, i0, j0, acc);
    __syncthreads();

    // Horner step 2: AC = AC*T3 + a3*I + a4*T + a5*T2
    mm64(AC, T3, i0, j0, acc);
    addpoly(acc, T, T2, P.a[3], P.a[4], P.a[5], i0, j0);
    __syncthreads();
    store_tile(AC, i0, j0, acc);
    __syncthreads();

    // Horner step 3 (final): out = AC*T3 + a0*I + a1*T + a2*T2 -> global
    mm64(AC, T3, i0, j0, acc);
    addpoly(acc, T, T2, P.a[0], P.a[1], P.a[2], i0, j0);
#pragma unroll
    for (int r = 0; r < 4; ++r)
        *reinterpret_cast<ulonglong2*>(go + (i0 + r) * 64 + j0) =
            make_ulonglong2(acc[r][0], acc[r][1]);
}

extern "C" void kernel_launch(void* const* d_in, const int* in_sizes, int n_in,
                              void* d_out, int out_size) {
    const float* in = (const float*)d_in[0];
    float* out = (float*)d_out;
    const int nmat = in_sizes[0] / 4096;   // 8192 matrices of 64x64

    // Chebyshev coefficients of log on [1,8], converted to monomial basis.
    Poly P;
    {
        const double alpha = 4.5, beta = 3.5;
        const double r = (alpha - sqrt(alpha * alpha - beta * beta)) / beta;
        double c[DEG + 1];
        c[0] = log(alpha / (1.0 + r * r));
        double rk = 1.0;
        for (int k = 1; k <= DEG; ++k) {
            rk *= r;
            c[k] = ((k & 1) ? 2.0 : -2.0) * rk / (double)k;
        }
        double mono[DEG + 1], Tm1[DEG + 1], Tc[DEG + 1], Tn[DEG + 1];
        for (int j = 0; j <= DEG; ++j) { mono[j] = 0; Tm1[j] = 0; Tc[j] = 0; }
        Tm1[0] = 1.0;            // T0
        Tc[1]  = 1.0;            // T1
        for (int j = 0; j <= DEG; ++j) mono[j] = c[0] * Tm1[j] + c[1] * Tc[j];
        for (int k = 2; k <= DEG; ++k) {
            for (int j = 0; j <= DEG; ++j) {
                double t = -Tm1[j];
                if (j > 0) t += 2.0 * Tc[j - 1];
                Tn[j] = t;
            }
            for (int j = 0; j <= DEG; ++j) {
                mono[j] += c[k] * Tn[j];
                Tm1[j] = Tc[j];
                Tc[j]  = Tn[j];
            }
        }
        for (int j = 0; j <= DEG; ++j) P.a[j] = (float)mono[j];
    }

    const size_t smem_bytes = 4 * MSZ * sizeof(float);   // 64 KB
    cudaFuncSetAttribute(logm_poly_kernel,
                         cudaFuncAttributeMaxDynamicSharedMemorySize,
                         (int)smem_bytes);
    logm_poly_kernel<<<nmat, 256, smem_bytes>>>(in, out, P);
}